// round 15
// baseline (speedup 1.0000x reference)
#include <cuda_runtime.h>
#include <cuda_fp16.h>
#include <math.h>
#include <stdint.h>

#define NUM_RANGES 256
#define KPR 512
#define DOPPLER 64
#define EMBED 16
#define IN_DIM 96
#define NROWS (NUM_RANGES * KPR)   // 131072

// Scratch (static device allocations are permitted)
__device__ __half g_Qf[NROWS * 64];         // fp16 Q, pre-scaled by log2(e)/8
__device__ __half g_Kf[NROWS * 64];         // fp16 K
__device__ float g_vs[NROWS];

// ---------------- mma.sync / ldmatrix helpers (sm_80+ PTX, sm_103-safe) -----
__device__ __forceinline__ unsigned smem_u32(const void* p) {
    unsigned a;
    asm("{ .reg .u64 t; cvta.to.shared.u64 t, %1; cvt.u32.u64 %0, t; }" : "=r"(a) : "l"(p));
    return a;
}
__device__ __forceinline__ void ldsm_x4(uint32_t* r, unsigned addr) {
    asm volatile("ldmatrix.sync.aligned.m8n8.x4.shared.b16 {%0,%1,%2,%3}, [%4];"
                 : "=r"(r[0]), "=r"(r[1]), "=r"(r[2]), "=r"(r[3]) : "r"(addr));
}
__device__ __forceinline__ void mma_f16(float* c, const uint32_t* a, const uint32_t* b) {
    asm volatile("mma.sync.aligned.m16n8k16.row.col.f32.f16.f16.f32 "
                 "{%0,%1,%2,%3}, {%4,%5,%6,%7}, {%8,%9}, {%0,%1,%2,%3};"
                 : "+f"(c[0]), "+f"(c[1]), "+f"(c[2]), "+f"(c[3])
                 : "r"(a[0]), "r"(a[1]), "r"(a[2]), "r"(a[3]), "r"(b[0]), "r"(b[1]));
}
__device__ __forceinline__ float ex2(float x) {
    float y; asm("ex2.approx.f32 %0, %1;" : "=f"(y) : "f"(x)); return y;
}
__device__ __forceinline__ unsigned pk(__half a, __half b) {
    return (unsigned)__half_as_ushort(a) | ((unsigned)__half_as_ushort(b) << 16);
}

#define SCQ 0.1803368801111244f   // log2(e) / sqrt(64)

// ---------------------------------------------------------------------------
// Kernel A: fused (weight-prep + gather + QK projection) via mma.sync.
// CTA = 128 rows x 128 outs x 96, 256 thr, 3 CTAs/SM.
// Phase 0: convert Wq/Wk to fp16 smem tile, wvs colsums, biases.
// ---------------------------------------------------------------------------
#define QP 104
#define ST_P 144                            // staging row pitch (bytes)
#define AX    0
#define AW    (AX + 128 * QP * 2)           // 26624
#define A_BB  (AW + 128 * QP * 2)           // 53248  float[128]
#define A_WV  (A_BB + 128 * 4)              // 53760  float[96]
#define A_BVS (A_WV + 96 * 4)               // 54144  float[1]
#define A_SMEM_BYTES (A_BVS + 64)           // 54208

__global__ void __launch_bounds__(256, 3) qkv_mma_kernel(
    const float* __restrict__ power, const int* __restrict__ ele_idx,
    const int* __restrict__ azi_idx, const float* __restrict__ ele_tab,
    const float* __restrict__ azi_tab,
    const float* __restrict__ Wq, const float* __restrict__ bq,
    const float* __restrict__ Wk, const float* __restrict__ bk,
    const float* __restrict__ Wv, const float* __restrict__ bv)
{
    extern __shared__ char smem[];
    const unsigned sbase = smem_u32(smem);
    __half* xf = (__half*)(smem + AX);
    __half* wf = (__half*)(smem + AW);
    float* sB   = (float*)(smem + A_BB);
    float* sWv  = (float*)(smem + A_WV);
    float* sBvs = (float*)(smem + A_BVS);

    const int tid  = threadIdx.x;
    const int row0 = blockIdx.x * 128;

    // ---- phase 0: weights -> fp16 smem (QP pitch), wvs, biases ----
    for (int i = tid; i < 64 * 96; i += 256) {
        int d = i / 96, f = i % 96;
        wf[d * QP + f]        = __float2half_rn(Wq[i]);
        wf[(64 + d) * QP + f] = __float2half_rn(Wk[i]);
    }
    if (tid < 96) {
        float s = 0.f;
        #pragma unroll 8
        for (int d = 0; d < 64; ++d) s += Wv[d * 96 + tid];
        sWv[tid] = s;
    } else if (tid >= 128 && tid < 192) {
        int t = tid - 128;
        sB[t] = bq[t]; sB[64 + t] = bk[t];
    } else if (tid >= 224) {
        int lane = tid - 224;
        float s = bv[lane * 2] + bv[lane * 2 + 1];
        #pragma unroll
        for (int o = 16; o > 0; o >>= 1) s += __shfl_xor_sync(0xffffffffu, s, o);
        if (lane == 0) *sBvs = s;
    }
    __syncthreads();

    // ---- gather + fp16 convert + inline vsum (2 threads per row) ----
    {
        const int row = tid >> 1, half = tid & 1;
        const int grow = row0 + row;
        unsigned* xrow = (unsigned*)(xf + row * QP);
        float vacc = 0.f;

        const float4* pv = (const float4*)(power + (size_t)grow * 64 + half * 32);
        #pragma unroll
        for (int u = 0; u < 8; ++u) {
            float4 v = pv[u];
            int f = half * 32 + u * 4;
            vacc += v.x * sWv[f]     + v.y * sWv[f + 1]
                  + v.z * sWv[f + 2] + v.w * sWv[f + 3];
            xrow[f >> 1]       = pk(__float2half_rn(v.x), __float2half_rn(v.y));
            xrow[(f >> 1) + 1] = pk(__float2half_rn(v.z), __float2half_rn(v.w));
        }
        const int eidx = half ? azi_idx[grow] : ele_idx[grow];
        const float4* ev = (const float4*)((half ? azi_tab : ele_tab) + (size_t)eidx * 16);
        const int fbase = 64 + half * 16;
        #pragma unroll
        for (int u = 0; u < 4; ++u) {
            float4 v = ev[u];
            int f = fbase + u * 4;
            vacc += v.x * sWv[f]     + v.y * sWv[f + 1]
                  + v.z * sWv[f + 2] + v.w * sWv[f + 3];
            xrow[f >> 1]       = pk(__float2half_rn(v.x), __float2half_rn(v.y));
            xrow[(f >> 1) + 1] = pk(__float2half_rn(v.z), __float2half_rn(v.w));
        }
        vacc += __shfl_xor_sync(0xffffffffu, vacc, 1);
        if (!half) g_vs[grow] = vacc + *sBvs;
    }
    __syncthreads();

    // ---- MMA: warp w = rows w*16..+15, all 128 outs, K=96 (6 chunks) ----
    const int w = tid >> 5, lane = tid & 31;
    const int qr = w * 16;
    const int arow = qr + (lane & 15);
    const int acol = (lane >> 4) * 8;
    const int brow = (lane & 7) + ((lane >> 4) << 3);
    const int bcol = ((lane >> 3) & 1) * 8;

    float C[16][4];
    #pragma unroll
    for (int nt = 0; nt < 16; ++nt)
        #pragma unroll
        for (int j = 0; j < 4; ++j) C[nt][j] = 0.f;

    #pragma unroll
    for (int dc = 0; dc < 6; ++dc) {
        uint32_t Af[4];
        unsigned aoff = (unsigned)(arow * QP + dc * 16 + acol) * 2;
        ldsm_x4(Af, sbase + AX + aoff);
        #pragma unroll
        for (int nt2 = 0; nt2 < 8; ++nt2) {
            unsigned boff = (unsigned)((nt2 * 16 + brow) * QP + dc * 16 + bcol) * 2;
            uint32_t Bf[4];
            ldsm_x4(Bf, sbase + AW + boff);
            mma_f16(C[nt2 * 2],     Af, Bf);
            mma_f16(C[nt2 * 2 + 1], Af, Bf + 2);
        }
    }
    __syncthreads();   // all ldsm reads done; smem now reusable as staging

    // ---- epilogue: bias + scale; Q,K -> fp16; stage in smem (ST_P pitch) ----
    {
        const int rl = qr + (lane >> 2);
        #pragma unroll
        for (int nt = 0; nt < 16; ++nt) {
            int cb = nt * 8 + (lane & 3) * 2;
            bool isQ = (nt < 8);
            float scl = isQ ? SCQ : 1.0f;
            int cc = isQ ? cb : (cb - 64);
            char* st = smem + (isQ ? AX : AW);
            float b0 = sB[cb], b1 = sB[cb + 1];
            float v00 = (C[nt][0] + b0) * scl, v01 = (C[nt][1] + b1) * scl;
            float v10 = (C[nt][2] + b0) * scl, v11 = (C[nt][3] + b1) * scl;
            *(unsigned*)(st + rl * ST_P + cc * 2) =
                pk(__float2half_rn(v00), __float2half_rn(v01));
            *(unsigned*)(st + (rl + 8) * ST_P + cc * 2) =
                pk(__float2half_rn(v10), __float2half_rn(v11));
        }
    }
    __syncthreads();

    // ---- copy-out: coalesced uint4 stores (2 arrays x 4 iters/thread) ----
    {
        const int offs[2] = {AX, AW};
        __half* dsts[2] = {g_Qf, g_Kf};
        #pragma unroll
        for (int a = 0; a < 2; ++a) {
            const char* src = smem + offs[a];
            __half* dst = dsts[a];
            #pragma unroll
            for (int it = 0; it < 4; ++it) {
                int i = tid + it * 256;
                int row = i >> 3, c = i & 7;
                uint4 v = *(const uint4*)(src + row * ST_P + c * 16);
                *(uint4*)&dst[(size_t)(row0 + row) * 64 + c * 8] = v;
            }
        }
    }
}

// ---------------------------------------------------------------------------
// Kernel B: mma.sync attention, 128 threads/CTA, 4 warps x 32 q rows.
// B fragments loaded once per (kt,dc,nt2), reused across both 16-row A-groups
// (halves redundant ldsm vs 8-warp shape). Full 512 k via 2-pass K streaming.
// grid = 1024 (r = bid>>2, qb = bid&3). 4 CTAs/SM.
// ---------------------------------------------------------------------------
#define QS 72
#define S_QF 0
#define S_KF (S_QF + 128 * QS * 2)          // 18432; K chunk: 256 rows x 144B
#define S_VS (S_KF + 256 * QS * 2)          // 55296; 512 floats
#define B_SMEM_BYTES (S_VS + 512 * 4)       // 57344

__global__ void __launch_bounds__(128, 4) attn_mma_kernel(float* __restrict__ out)
{
    extern __shared__ char smem[];
    const unsigned sbase = smem_u32(smem);
    const int tid = threadIdx.x;
    const int r  = blockIdx.x >> 2;
    const int qb = blockIdx.x & 3;
    const int kbase = r * KPR;
    const int qrow0 = kbase + qb * 128;

    const uint4* Qf4 = (const uint4*)g_Qf;
    const uint4* Kf4 = (const uint4*)g_Kf;

    // ---- load Qf, vsum (all 512), K chunk 0 (rows 0..255) ----
    for (int i = tid; i < 1024; i += 128) {
        int row = i >> 3, c = i & 7;
        *(uint4*)(smem + S_QF + row * QS * 2 + c * 16) = Qf4[(size_t)(qrow0 + row) * 8 + c];
    }
    for (int i = tid; i < 512; i += 128)
        *(float*)(smem + S_VS + i * 4) = g_vs[kbase + i];
    for (int i = tid; i < 2048; i += 128) {
        int row = i >> 3, c = i & 7;
        *(uint4*)(smem + S_KF + row * QS * 2 + c * 16) = Kf4[(size_t)(kbase + row) * 8 + c];
    }
    __syncthreads();

    const int w = tid >> 5, lane = tid & 31;
    const int qr = w * 32;                   // 32 q rows per warp (2 groups of 16)

    // ---- resident A fragments (Qf): 2 groups x 4 d-chunks ----
    uint32_t Af[2][4][4];
    {
        int acol = (lane >> 4) * 8;
        #pragma unroll
        for (int g = 0; g < 2; ++g) {
            int arow = qr + g * 16 + (lane & 15);
            #pragma unroll
            for (int dc = 0; dc < 4; ++dc) {
                unsigned off = (unsigned)(arow * QS + dc * 16 + acol) * 2;
                ldsm_x4(Af[g][dc], sbase + S_QF + off);
            }
        }
    }

    float se[2][2] = {{0.f, 0.f}, {0.f, 0.f}};
    float sv[2][2] = {{0.f, 0.f}, {0.f, 0.f}};
    const int brow = (lane & 7) + ((lane >> 4) << 3);
    const int bcol = ((lane >> 3) & 1) * 8;
    const float* vsp = (const float*)(smem + S_VS);
    const int c0off = 2 * (lane & 3);

    for (int kc = 0; kc < 2; ++kc) {
        if (kc == 1) {
            __syncthreads();   // pass-0 ldsm complete before overwrite
            for (int i = tid; i < 2048; i += 128) {
                int row = i >> 3, c = i & 7;
                *(uint4*)(smem + S_KF + row * QS * 2 + c * 16) =
                    Kf4[(size_t)(kbase + 256 + row) * 8 + c];
            }
            __syncthreads();
        }

        #pragma unroll
        for (int kt = 0; kt < 8; ++kt) {      // 32 k-cols per chunk
            float C[2][4][4];
            #pragma unroll
            for (int g = 0; g < 2; ++g)
                #pragma unroll
                for (int nt = 0; nt < 4; ++nt)
                    #pragma unroll
                    for (int j = 0; j < 4; ++j) C[g][nt][j] = 0.f;

            #pragma unroll
            for (int dc = 0; dc < 4; ++dc) {
                #pragma unroll
                for (int nt2 = 0; nt2 < 2; ++nt2) {
                    int n0 = kt * 32 + nt2 * 16;
                    unsigned off = (unsigned)((n0 + brow) * QS + dc * 16 + bcol) * 2;
                    uint32_t Bf[4];
                    ldsm_x4(Bf, sbase + S_KF + off);
                    #pragma unroll
                    for (int g = 0; g < 2; ++g) {
                        mma_f16(C[g][nt2 * 2],     Af[g][dc], Bf);
                        mma_f16(C[g][nt2 * 2 + 1], Af[g][dc], Bf + 2);
                    }
                }
            }

            // epilogue for this 32-k chunk (scores already in log2 units)
            #pragma unroll
            for (int nt = 0; nt < 4; ++nt) {
                int col0 = kc * 256 + kt * 32 + nt * 8 + c0off;
                float2 vv = *(const float2*)(vsp + col0);
                #pragma unroll
                for (int g = 0; g < 2; ++g) {
                    float e0 = ex2(C[g][nt][0]);
                    float e1 = ex2(C[g][nt][1]);
                    float e2 = ex2(C[g][nt][2]);
                    float e3 = ex2(C[g][nt][3]);
                    se[g][0] += e0 + e1; sv[g][0] += e0 * vv.x + e1 * vv.y;
                    se[g][1] += e2 + e3; sv[g][1] += e2 * vv.x + e3 * vv.y;
                }
            }
        }
    }

    // quad reduce, direct output
    #pragma unroll
    for (int o = 1; o <= 2; o <<= 1) {
        #pragma unroll
        for (int g = 0; g < 2; ++g) {
            se[g][0] += __shfl_xor_sync(0xffffffffu, se[g][0], o);
            sv[g][0] += __shfl_xor_sync(0xffffffffu, sv[g][0], o);
            se[g][1] += __shfl_xor_sync(0xffffffffu, se[g][1], o);
            sv[g][1] += __shfl_xor_sync(0xffffffffu, sv[g][1], o);
        }
    }
    if ((lane & 3) == 0) {
        #pragma unroll
        for (int g = 0; g < 2; ++g) {
            int row = qrow0 + qr + g * 16 + (lane >> 2);
            out[row]     = sv[g][0] / se[g][0];
            out[row + 8] = sv[g][1] / se[g][1];
        }
    }
}

// ---------------------------------------------------------------------------
// Launch
// ---------------------------------------------------------------------------
extern "C" void kernel_launch(void* const* d_in, const int* in_sizes, int n_in,
                              void* d_out, int out_size)
{
    const float* power   = (const float*)d_in[0];
    const int*   ele_idx = (const int*)  d_in[1];
    // d_in[2] = range_indices (unused by reference)
    const int*   azi_idx = (const int*)  d_in[3];
    const float* ele_tab = (const float*)d_in[4];
    const float* azi_tab = (const float*)d_in[5];
    const float* Wq      = (const float*)d_in[6];
    const float* bq      = (const float*)d_in[7];
    const float* Wk      = (const float*)d_in[8];
    const float* bk      = (const float*)d_in[9];
    const float* Wv      = (const float*)d_in[10];
    const float* bv      = (const float*)d_in[11];
    float* out = (float*)d_out;

    cudaFuncSetAttribute(qkv_mma_kernel, cudaFuncAttributeMaxDynamicSharedMemorySize, A_SMEM_BYTES);
    cudaFuncSetAttribute(attn_mma_kernel, cudaFuncAttributeMaxDynamicSharedMemorySize, B_SMEM_BYTES);

    qkv_mma_kernel<<<NROWS / 128, 256, A_SMEM_BYTES>>>(
        power, ele_idx, azi_idx, ele_tab, azi_tab, Wq, bq, Wk, bk, Wv, bv);
    attn_mma_kernel<<<NUM_RANGES * 4, 128, B_SMEM_BYTES>>>(out);
}

// round 16
// speedup vs baseline: 1.0865x; 1.0865x over previous
#include <cuda_runtime.h>
#include <cuda_fp16.h>
#include <math.h>
#include <stdint.h>

#define NUM_RANGES 256
#define KPR 512
#define DOPPLER 64
#define EMBED 16
#define IN_DIM 96
#define NROWS (NUM_RANGES * KPR)   // 131072

// Scratch (static device allocations are permitted)
__device__ __half g_Qf[NROWS * 64];         // fp16 Q, pre-scaled by log2(e)/8
__device__ __half g_Kf[NROWS * 64];         // fp16 K
__device__ float g_vs[NROWS];

// ---------------- mma.sync / ldmatrix helpers (sm_80+ PTX, sm_103-safe) -----
__device__ __forceinline__ unsigned smem_u32(const void* p) {
    unsigned a;
    asm("{ .reg .u64 t; cvta.to.shared.u64 t, %1; cvt.u32.u64 %0, t; }" : "=r"(a) : "l"(p));
    return a;
}
__device__ __forceinline__ void ldsm_x4(uint32_t* r, unsigned addr) {
    asm volatile("ldmatrix.sync.aligned.m8n8.x4.shared.b16 {%0,%1,%2,%3}, [%4];"
                 : "=r"(r[0]), "=r"(r[1]), "=r"(r[2]), "=r"(r[3]) : "r"(addr));
}
__device__ __forceinline__ void mma_f16(float* c, const uint32_t* a, const uint32_t* b) {
    asm volatile("mma.sync.aligned.m16n8k16.row.col.f32.f16.f16.f32 "
                 "{%0,%1,%2,%3}, {%4,%5,%6,%7}, {%8,%9}, {%0,%1,%2,%3};"
                 : "+f"(c[0]), "+f"(c[1]), "+f"(c[2]), "+f"(c[3])
                 : "r"(a[0]), "r"(a[1]), "r"(a[2]), "r"(a[3]), "r"(b[0]), "r"(b[1]));
}
__device__ __forceinline__ float ex2(float x) {
    float y; asm("ex2.approx.f32 %0, %1;" : "=f"(y) : "f"(x)); return y;
}
__device__ __forceinline__ unsigned pk(__half a, __half b) {
    return (unsigned)__half_as_ushort(a) | ((unsigned)__half_as_ushort(b) << 16);
}

#define SCQ 0.1803368801111244f   // log2(e) / sqrt(64)

// ---------------------------------------------------------------------------
// Kernel A: fused (weight-prep + gather + QK projection) via mma.sync.
// CTA = 128 rows x 128 outs x 96, 256 thr, 3 CTAs/SM.
// Phase 0: convert Wq/Wk to fp16 smem tile, wvs colsums, biases.
// ---------------------------------------------------------------------------
#define QP 104
#define ST_P 144                            // staging row pitch (bytes)
#define AX    0
#define AW    (AX + 128 * QP * 2)           // 26624
#define A_BB  (AW + 128 * QP * 2)           // 53248  float[128]
#define A_WV  (A_BB + 128 * 4)              // 53760  float[96]
#define A_BVS (A_WV + 96 * 4)               // 54144  float[1]
#define A_SMEM_BYTES (A_BVS + 64)           // 54208

__global__ void __launch_bounds__(256, 3) qkv_mma_kernel(
    const float* __restrict__ power, const int* __restrict__ ele_idx,
    const int* __restrict__ azi_idx, const float* __restrict__ ele_tab,
    const float* __restrict__ azi_tab,
    const float* __restrict__ Wq, const float* __restrict__ bq,
    const float* __restrict__ Wk, const float* __restrict__ bk,
    const float* __restrict__ Wv, const float* __restrict__ bv)
{
    extern __shared__ char smem[];
    const unsigned sbase = smem_u32(smem);
    __half* xf = (__half*)(smem + AX);
    __half* wf = (__half*)(smem + AW);
    float* sB   = (float*)(smem + A_BB);
    float* sWv  = (float*)(smem + A_WV);
    float* sBvs = (float*)(smem + A_BVS);

    const int tid  = threadIdx.x;
    const int row0 = blockIdx.x * 128;

    // ---- phase 0: weights -> fp16 smem (QP pitch), wvs, biases ----
    for (int i = tid; i < 64 * 96; i += 256) {
        int d = i / 96, f = i % 96;
        wf[d * QP + f]        = __float2half_rn(Wq[i]);
        wf[(64 + d) * QP + f] = __float2half_rn(Wk[i]);
    }
    if (tid < 96) {
        float s = 0.f;
        #pragma unroll 8
        for (int d = 0; d < 64; ++d) s += Wv[d * 96 + tid];
        sWv[tid] = s;
    } else if (tid >= 128 && tid < 192) {
        int t = tid - 128;
        sB[t] = bq[t]; sB[64 + t] = bk[t];
    } else if (tid >= 224) {
        int lane = tid - 224;
        float s = bv[lane * 2] + bv[lane * 2 + 1];
        #pragma unroll
        for (int o = 16; o > 0; o >>= 1) s += __shfl_xor_sync(0xffffffffu, s, o);
        if (lane == 0) *sBvs = s;
    }
    __syncthreads();

    // ---- gather + fp16 convert + inline vsum (2 threads per row) ----
    {
        const int row = tid >> 1, half = tid & 1;
        const int grow = row0 + row;
        unsigned* xrow = (unsigned*)(xf + row * QP);
        float vacc = 0.f;

        const float4* pv = (const float4*)(power + (size_t)grow * 64 + half * 32);
        #pragma unroll
        for (int u = 0; u < 8; ++u) {
            float4 v = pv[u];
            int f = half * 32 + u * 4;
            vacc += v.x * sWv[f]     + v.y * sWv[f + 1]
                  + v.z * sWv[f + 2] + v.w * sWv[f + 3];
            xrow[f >> 1]       = pk(__float2half_rn(v.x), __float2half_rn(v.y));
            xrow[(f >> 1) + 1] = pk(__float2half_rn(v.z), __float2half_rn(v.w));
        }
        const int eidx = half ? azi_idx[grow] : ele_idx[grow];
        const float4* ev = (const float4*)((half ? azi_tab : ele_tab) + (size_t)eidx * 16);
        const int fbase = 64 + half * 16;
        #pragma unroll
        for (int u = 0; u < 4; ++u) {
            float4 v = ev[u];
            int f = fbase + u * 4;
            vacc += v.x * sWv[f]     + v.y * sWv[f + 1]
                  + v.z * sWv[f + 2] + v.w * sWv[f + 3];
            xrow[f >> 1]       = pk(__float2half_rn(v.x), __float2half_rn(v.y));
            xrow[(f >> 1) + 1] = pk(__float2half_rn(v.z), __float2half_rn(v.w));
        }
        vacc += __shfl_xor_sync(0xffffffffu, vacc, 1);
        if (!half) g_vs[grow] = vacc + *sBvs;
    }
    __syncthreads();

    // ---- MMA: warp w = rows w*16..+15, all 128 outs, K=96 (6 chunks) ----
    const int w = tid >> 5, lane = tid & 31;
    const int qr = w * 16;
    const int arow = qr + (lane & 15);
    const int acol = (lane >> 4) * 8;
    const int brow = (lane & 7) + ((lane >> 4) << 3);
    const int bcol = ((lane >> 3) & 1) * 8;

    float C[16][4];
    #pragma unroll
    for (int nt = 0; nt < 16; ++nt)
        #pragma unroll
        for (int j = 0; j < 4; ++j) C[nt][j] = 0.f;

    #pragma unroll
    for (int dc = 0; dc < 6; ++dc) {
        uint32_t Af[4];
        unsigned aoff = (unsigned)(arow * QP + dc * 16 + acol) * 2;
        ldsm_x4(Af, sbase + AX + aoff);
        #pragma unroll
        for (int nt2 = 0; nt2 < 8; ++nt2) {
            unsigned boff = (unsigned)((nt2 * 16 + brow) * QP + dc * 16 + bcol) * 2;
            uint32_t Bf[4];
            ldsm_x4(Bf, sbase + AW + boff);
            mma_f16(C[nt2 * 2],     Af, Bf);
            mma_f16(C[nt2 * 2 + 1], Af, Bf + 2);
        }
    }
    __syncthreads();   // all ldsm reads done; smem now reusable as staging

    // ---- epilogue: bias + scale; Q,K -> fp16; stage in smem (ST_P pitch) ----
    {
        const int rl = qr + (lane >> 2);
        #pragma unroll
        for (int nt = 0; nt < 16; ++nt) {
            int cb = nt * 8 + (lane & 3) * 2;
            bool isQ = (nt < 8);
            float scl = isQ ? SCQ : 1.0f;
            int cc = isQ ? cb : (cb - 64);
            char* st = smem + (isQ ? AX : AW);
            float b0 = sB[cb], b1 = sB[cb + 1];
            float v00 = (C[nt][0] + b0) * scl, v01 = (C[nt][1] + b1) * scl;
            float v10 = (C[nt][2] + b0) * scl, v11 = (C[nt][3] + b1) * scl;
            *(unsigned*)(st + rl * ST_P + cc * 2) =
                pk(__float2half_rn(v00), __float2half_rn(v01));
            *(unsigned*)(st + (rl + 8) * ST_P + cc * 2) =
                pk(__float2half_rn(v10), __float2half_rn(v11));
        }
    }
    __syncthreads();

    // ---- copy-out: coalesced uint4 stores (2 arrays x 4 iters/thread) ----
    {
        const int offs[2] = {AX, AW};
        __half* dsts[2] = {g_Qf, g_Kf};
        #pragma unroll
        for (int a = 0; a < 2; ++a) {
            const char* src = smem + offs[a];
            __half* dst = dsts[a];
            #pragma unroll
            for (int it = 0; it < 4; ++it) {
                int i = tid + it * 256;
                int row = i >> 3, c = i & 7;
                uint4 v = *(const uint4*)(src + row * ST_P + c * 16);
                *(uint4*)&dst[(size_t)(row0 + row) * 64 + c * 8] = v;
            }
        }
    }
}

// ---------------------------------------------------------------------------
// Kernel B: mma.sync attention (proven 256-thread shape, 8 warps x 16 q rows).
// Full 512 k per CTA via 2-pass K streaming, direct output.
// grid = 1024 (r = bid>>2, qb = bid&3). 4 CTAs/SM.
// ---------------------------------------------------------------------------
#define QS 72
#define S_QF 0
#define S_KF (S_QF + 128 * QS * 2)          // 18432; K chunk: 256 rows x 144B
#define S_VS (S_KF + 256 * QS * 2)          // 55296; 512 floats
#define B_SMEM_BYTES (S_VS + 512 * 4)       // 57344

__global__ void __launch_bounds__(256, 4) attn_mma_kernel(float* __restrict__ out)
{
    extern __shared__ char smem[];
    const unsigned sbase = smem_u32(smem);
    const int tid = threadIdx.x;
    const int r  = blockIdx.x >> 2;
    const int qb = blockIdx.x & 3;
    const int kbase = r * KPR;
    const int qrow0 = kbase + qb * 128;

    const uint4* Qf4 = (const uint4*)g_Qf;
    const uint4* Kf4 = (const uint4*)g_Kf;

    // ---- load Qf, vsum (all 512), K chunk 0 (rows 0..255) ----
    for (int i = tid; i < 1024; i += 256) {
        int row = i >> 3, c = i & 7;
        *(uint4*)(smem + S_QF + row * QS * 2 + c * 16) = Qf4[(size_t)(qrow0 + row) * 8 + c];
    }
    for (int i = tid; i < 512; i += 256)
        *(float*)(smem + S_VS + i * 4) = g_vs[kbase + i];
    for (int i = tid; i < 2048; i += 256) {
        int row = i >> 3, c = i & 7;
        *(uint4*)(smem + S_KF + row * QS * 2 + c * 16) = Kf4[(size_t)(kbase + row) * 8 + c];
    }
    __syncthreads();

    const int w = tid >> 5, lane = tid & 31;
    const int qr = w * 16;

    // ---- resident A fragments (Qf), 4 d-chunks ----
    uint32_t Af[4][4];
    {
        int arow = qr + (lane & 15);
        int acol = (lane >> 4) * 8;
        #pragma unroll
        for (int dc = 0; dc < 4; ++dc) {
            unsigned off = (unsigned)(arow * QS + dc * 16 + acol) * 2;
            ldsm_x4(Af[dc], sbase + S_QF + off);
        }
    }

    float se0 = 0.f, sv0 = 0.f, se1 = 0.f, sv1 = 0.f;
    const int brow = (lane & 7) + ((lane >> 4) << 3);
    const int bcol = ((lane >> 3) & 1) * 8;
    const float* vsp = (const float*)(smem + S_VS);
    const int c0off = 2 * (lane & 3);

    for (int kc = 0; kc < 2; ++kc) {
        if (kc == 1) {
            __syncthreads();   // pass-0 ldsm complete before overwrite
            for (int i = tid; i < 2048; i += 256) {
                int row = i >> 3, c = i & 7;
                *(uint4*)(smem + S_KF + row * QS * 2 + c * 16) =
                    Kf4[(size_t)(kbase + 256 + row) * 8 + c];
            }
            __syncthreads();
        }

        #pragma unroll
        for (int kt = 0; kt < 8; ++kt) {      // 32 k-cols per chunk
            float C[4][4];
            #pragma unroll
            for (int nt = 0; nt < 4; ++nt)
                #pragma unroll
                for (int j = 0; j < 4; ++j) C[nt][j] = 0.f;

            #pragma unroll
            for (int dc = 0; dc < 4; ++dc) {
                #pragma unroll
                for (int nt2 = 0; nt2 < 2; ++nt2) {
                    int n0 = kt * 32 + nt2 * 16;
                    unsigned off = (unsigned)((n0 + brow) * QS + dc * 16 + bcol) * 2;
                    uint32_t Bf[4];
                    ldsm_x4(Bf, sbase + S_KF + off);
                    mma_f16(C[nt2 * 2],     Af[dc], Bf);
                    mma_f16(C[nt2 * 2 + 1], Af[dc], Bf + 2);
                }
            }

            // epilogue for this 32-k chunk (scores already in log2 units)
            #pragma unroll
            for (int nt = 0; nt < 4; ++nt) {
                int col0 = kc * 256 + kt * 32 + nt * 8 + c0off;
                float2 vv = *(const float2*)(vsp + col0);
                float e0 = ex2(C[nt][0]);
                float e1 = ex2(C[nt][1]);
                float e2 = ex2(C[nt][2]);
                float e3 = ex2(C[nt][3]);
                se0 += e0 + e1; sv0 += e0 * vv.x + e1 * vv.y;
                se1 += e2 + e3; sv1 += e2 * vv.x + e3 * vv.y;
            }
        }
    }

    // quad reduce, direct output
    #pragma unroll
    for (int o = 1; o <= 2; o <<= 1) {
        se0 += __shfl_xor_sync(0xffffffffu, se0, o);
        sv0 += __shfl_xor_sync(0xffffffffu, sv0, o);
        se1 += __shfl_xor_sync(0xffffffffu, se1, o);
        sv1 += __shfl_xor_sync(0xffffffffu, sv1, o);
    }
    if ((lane & 3) == 0) {
        int row = qrow0 + qr + (lane >> 2);
        out[row]     = sv0 / se0;
        out[row + 8] = sv1 / se1;
    }
}

// ---------------------------------------------------------------------------
// Launch
// ---------------------------------------------------------------------------
extern "C" void kernel_launch(void* const* d_in, const int* in_sizes, int n_in,
                              void* d_out, int out_size)
{
    const float* power   = (const float*)d_in[0];
    const int*   ele_idx = (const int*)  d_in[1];
    // d_in[2] = range_indices (unused by reference)
    const int*   azi_idx = (const int*)  d_in[3];
    const float* ele_tab = (const float*)d_in[4];
    const float* azi_tab = (const float*)d_in[5];
    const float* Wq      = (const float*)d_in[6];
    const float* bq      = (const float*)d_in[7];
    const float* Wk      = (const float*)d_in[8];
    const float* bk      = (const float*)d_in[9];
    const float* Wv      = (const float*)d_in[10];
    const float* bv      = (const float*)d_in[11];
    float* out = (float*)d_out;

    cudaFuncSetAttribute(qkv_mma_kernel, cudaFuncAttributeMaxDynamicSharedMemorySize, A_SMEM_BYTES);
    cudaFuncSetAttribute(attn_mma_kernel, cudaFuncAttributeMaxDynamicSharedMemorySize, B_SMEM_BYTES);

    qkv_mma_kernel<<<NROWS / 128, 256, A_SMEM_BYTES>>>(
        power, ele_idx, azi_idx, ele_tab, azi_tab, Wq, bq, Wk, bk, Wv, bv);
    attn_mma_kernel<<<NUM_RANGES * 4, 256, B_SMEM_BYTES>>>(out);
}